// round 5
// baseline (speedup 1.0000x reference)
#include <cuda_runtime.h>
#include <cstdint>

// LmulLinear: out[m,p] = sum_k bitcast_f32(bits(x[m,k]) + bits(w[p,k]) - OFFSET) + bias[p]
// M=256, K=512, P=512.
//
// R5: cross-CTA split-K x4 (512 CTAs x 256 thr -> ~28 warps/SM), scalar IADD+FADD
//     inner loop (2 instr/MAC, dual-pipe balanced), partials in __device__ scratch,
//     deterministic second-kernel reduction (+bias).

#define M_DIM 256
#define K_DIM 512
#define P_DIM 512
#define BM 32
#define BN 32
#define KSPLIT 4
#define KG (K_DIM / KSPLIT)     // 128 k per CTA
#define SROW (KG + 4)           // 132 words: (4r + c) mod 32 layout, conflict-light LDS.128
#define TILE_WORDS (BM * SROW)  // 4224
#define SMEM_BYTES (2 * TILE_WORDS * 4)  // 33792 B

__device__ float g_partial[KSPLIT * M_DIM * P_DIM];  // 2 MB scratch

static __device__ __forceinline__ float u2f(uint32_t u) { return __uint_as_float(u); }

extern __shared__ uint32_t smem[];

__global__ void __launch_bounds__(256)
lmul_partial_kernel(const float* __restrict__ x,
                    const float* __restrict__ w)
{
    constexpr uint32_t OFFSET = 1064828928u;  // 0x3F780000

    const int tid = threadIdx.x;
    const int tx  = tid & 15;        // p cols: tx, tx+16
    const int ty  = tid >> 4;        // m rows: ty, ty+16
    const int m0  = blockIdx.y * BM;
    const int p0  = blockIdx.x * BN;
    const int ks  = blockIdx.z;
    const int kbase = ks * KG;

    uint32_t* As = smem;               // [BM][SROW]
    uint32_t* Bs = smem + TILE_WORDS;  // [BN][SROW], offset-folded

    const uint32_t* __restrict__ xu = reinterpret_cast<const uint32_t*>(x);
    const uint32_t* __restrict__ wu = reinterpret_cast<const uint32_t*>(w);

    // ---- load tiles: each 32 rows x 32 uint4; 4 uint4 per thread per tile ----
    #pragma unroll
    for (int i = 0; i < 4; i++) {
        int idx = tid + i * 256;        // 0..1023
        int row = idx >> 5;
        int c   = (idx & 31) * 4;
        uint4 va = *reinterpret_cast<const uint4*>(&xu[(m0 + row) * K_DIM + kbase + c]);
        *reinterpret_cast<uint4*>(&As[row * SROW + c]) = va;
        uint4 vb = *reinterpret_cast<const uint4*>(&wu[(p0 + row) * K_DIM + kbase + c]);
        vb.x -= OFFSET; vb.y -= OFFSET; vb.z -= OFFSET; vb.w -= OFFSET;
        *reinterpret_cast<uint4*>(&Bs[row * SROW + c]) = vb;
    }
    __syncthreads();

    // ---- 2x2 microtile: rows {ty, ty+16}, cols {tx, tx+16} ----
    const uint32_t* a0p = As + ty * SROW;
    const uint32_t* a1p = As + (ty + 16) * SROW;
    const uint32_t* b0p = Bs + tx * SROW;
    const uint32_t* b1p = Bs + (tx + 16) * SROW;

    float acc00 = 0.f, acc01 = 0.f, acc10 = 0.f, acc11 = 0.f;

    #pragma unroll 8
    for (int j = 0; j < KG / 4; j++) {
        uint4 a0 = *reinterpret_cast<const uint4*>(a0p + 4 * j);
        uint4 a1 = *reinterpret_cast<const uint4*>(a1p + 4 * j);
        uint4 b0 = *reinterpret_cast<const uint4*>(b0p + 4 * j);
        uint4 b1 = *reinterpret_cast<const uint4*>(b1p + 4 * j);

        acc00 += u2f(a0.x + b0.x); acc01 += u2f(a0.x + b1.x);
        acc10 += u2f(a1.x + b0.x); acc11 += u2f(a1.x + b1.x);

        acc00 += u2f(a0.y + b0.y); acc01 += u2f(a0.y + b1.y);
        acc10 += u2f(a1.y + b0.y); acc11 += u2f(a1.y + b1.y);

        acc00 += u2f(a0.z + b0.z); acc01 += u2f(a0.z + b1.z);
        acc10 += u2f(a1.z + b0.z); acc11 += u2f(a1.z + b1.z);

        acc00 += u2f(a0.w + b0.w); acc01 += u2f(a0.w + b1.w);
        acc10 += u2f(a1.w + b0.w); acc11 += u2f(a1.w + b1.w);
    }

    // ---- write partials (each (ks,m,p) written by exactly one thread) ----
    float* part = g_partial + ks * (M_DIM * P_DIM);
    const int m_a = m0 + ty;
    const int m_b = m0 + ty + 16;
    const int p_a = p0 + tx;
    const int p_b = p0 + tx + 16;
    part[m_a * P_DIM + p_a] = acc00;
    part[m_a * P_DIM + p_b] = acc01;
    part[m_b * P_DIM + p_a] = acc10;
    part[m_b * P_DIM + p_b] = acc11;
}

__global__ void __launch_bounds__(256)
lmul_reduce_kernel(const float* __restrict__ bias,
                   float* __restrict__ out)
{
    // 256x512 outputs, float4-vectorized: 32768 float4, grid 128 x 256 threads.
    const int idx4 = blockIdx.x * 256 + threadIdx.x;      // 0..32767
    const int base = idx4 * 4;
    const int p = base & (P_DIM - 1);

    const float4* p0 = reinterpret_cast<const float4*>(g_partial + 0 * M_DIM * P_DIM + base);
    const float4* p1 = reinterpret_cast<const float4*>(g_partial + 1 * M_DIM * P_DIM + base);
    const float4* p2 = reinterpret_cast<const float4*>(g_partial + 2 * M_DIM * P_DIM + base);
    const float4* p3 = reinterpret_cast<const float4*>(g_partial + 3 * M_DIM * P_DIM + base);

    float4 v0 = *p0, v1 = *p1, v2 = *p2, v3 = *p3;
    float4 b  = *reinterpret_cast<const float4*>(bias + p);

    float4 r;
    r.x = ((v0.x + v1.x) + (v2.x + v3.x)) + b.x;
    r.y = ((v0.y + v1.y) + (v2.y + v3.y)) + b.y;
    r.z = ((v0.z + v1.z) + (v2.z + v3.z)) + b.z;
    r.w = ((v0.w + v1.w) + (v2.w + v3.w)) + b.w;

    *reinterpret_cast<float4*>(out + base) = r;
}

extern "C" void kernel_launch(void* const* d_in, const int* in_sizes, int n_in,
                              void* d_out, int out_size)
{
    const float* x    = (const float*)d_in[0];   // (256, 512)
    const float* w    = (const float*)d_in[1];   // (512, 512)
    const float* bias = (const float*)d_in[2];   // (512,)
    float* out = (float*)d_out;                  // (256, 512)

    dim3 grid1(P_DIM / BN, M_DIM / BM, KSPLIT);  // (16, 8, 4) = 512 CTAs
    lmul_partial_kernel<<<grid1, 256, SMEM_BYTES>>>(x, w);

    dim3 grid2((M_DIM * P_DIM) / (256 * 4));     // 128 CTAs
    lmul_reduce_kernel<<<grid2, 256>>>(bias, out);
}